// round 7
// baseline (speedup 1.0000x reference)
#include <cuda_runtime.h>
#include <math.h>

#define N_STATES      25
#define N_X           64            // obs < 50; padded to 64 rows
#define PITCH2        13            // float2 per x-row: 12 state-pairs + 1 pad (26 floats, even -> LDS.64 aligned, good bank spread)
#define LUT2_SIZE     (N_X * PITCH2)
#define BLOCK_THREADS 256

// Transposed LUT in float2 units: g_lut2[x*PITCH2 + p] = {nb(s=1+2p), nb(s=2+2p)}, p=0..11.
// (allocation-free rule: __device__ global scratch)
__device__ float2 g_lut2[LUT2_SIZE];

// Build the transposed 64 x 24 log-prob table in fp32 (few-ulp accurate, >>1e-3 margin).
// One thread per (x, state) scalar entry; pad pair (p=12) zeroed.
__global__ void build_lut_kernel(const float* __restrict__ means,
                                 const float* __restrict__ phis) {
    int idx = blockIdx.x * blockDim.x + threadIdx.x;   // over N_X * 26 scalars
    if (idx >= N_X * 2 * PITCH2) return;
    int x  = idx / (2 * PITCH2);
    int c  = idx % (2 * PITCH2);                        // scalar column 0..25
    float v = 0.0f;
    if (c < 24) {
        int s = c + 1;                                  // states 1..24
        float mu  = means[s];
        float phi = phis[s];
        float xf  = (float)x;
        float inv = 1.0f / (phi + mu);
        v = lgammaf(xf + phi) - lgammaf(phi) - lgammaf(xf + 1.0f)
          + phi * logf(phi * inv)
          + xf  * logf(mu  * inv);
    }
    ((float*)g_lut2)[x * 2 * PITCH2 + c] = v;
}

// Main kernel: out[s][i] = LUT[s][obs[i]].
// One int4 group (4 spots) per thread, deep oversubscription (~26 blocks/SM queued).
// Row 0 (bookend) computed arithmetically. Rows 1..24 gathered as 12 state-pairs
// per obs value via LDS.64 from the x-major LUT (half the LDS instruction count
// of the state-major layout).
__global__ void __launch_bounds__(BLOCK_THREADS, 8)
emit_kernel(const int* __restrict__ obs,
            float* __restrict__ out,
            int n_groups,        // n_spots / 4
            long long n_spots) {
    __shared__ float2 lut2[LUT2_SIZE];
    #pragma unroll
    for (int i = threadIdx.x; i < LUT2_SIZE; i += BLOCK_THREADS)
        lut2[i] = g_lut2[i];
    __syncthreads();

    int g = blockIdx.x * BLOCK_THREADS + threadIdx.x;
    if (g >= n_groups) return;

    int4 o = ((const int4*)obs)[g];

    // Row 0: bookend, pure ALU (no smem traffic).
    {
        float4 v;
        v.x = (o.x > 0) ? -100000.0f : 0.0f;
        v.y = (o.y > 0) ? -100000.0f : 0.0f;
        v.z = (o.z > 0) ? -100000.0f : 0.0f;
        v.w = (o.w > 0) ? -100000.0f : 0.0f;
        ((float4*)out)[g] = v;
    }

    const float2* rx = lut2 + o.x * PITCH2;
    const float2* ry = lut2 + o.y * PITCH2;
    const float2* rz = lut2 + o.z * PITCH2;
    const float2* rw = lut2 + o.w * PITCH2;

    #pragma unroll
    for (int p = 0; p < 12; p++) {
        float2 ax = rx[p];
        float2 ay = ry[p];
        float2 az = rz[p];
        float2 aw = rw[p];
        long long s1 = (long long)(1 + 2 * p) * n_spots;
        long long s2 = (long long)(2 + 2 * p) * n_spots;
        float4 v1 = make_float4(ax.x, ay.x, az.x, aw.x);
        float4 v2 = make_float4(ax.y, ay.y, az.y, aw.y);
        ((float4*)(out + s1))[g] = v1;
        ((float4*)(out + s2))[g] = v2;
    }
}

// Scalar fallback only if n_spots % 4 != 0 (never hit for N_SPOTS=4M).
__global__ void emit_tail_kernel(const int* __restrict__ obs,
                                 float* __restrict__ out,
                                 int tail_start, int n_spots_i,
                                 long long n_spots) {
    int i = tail_start + blockIdx.x * blockDim.x + threadIdx.x;
    if (i >= n_spots_i) return;
    int x = obs[i];
    out[i] = (x > 0) ? -100000.0f : 0.0f;
    const float* row = (const float*)(g_lut2 + x * PITCH2);
    #pragma unroll
    for (int s = 1; s < N_STATES; s++)
        out[(long long)s * n_spots + i] = row[s - 1];
}

extern "C" void kernel_launch(void* const* d_in, const int* in_sizes, int n_in,
                              void* d_out, int out_size) {
    const float* state_means = (const float*)d_in[0];
    const float* state_phis  = (const float*)d_in[1];
    const int*   obs         = (const int*)d_in[2];
    float*       out         = (float*)d_out;

    int n_spots_i = in_sizes[2];
    long long n_spots = (long long)n_spots_i;

    int build_elems = N_X * 2 * PITCH2;
    build_lut_kernel<<<(build_elems + 255) / 256, 256>>>(state_means, state_phis);

    int n_groups = n_spots_i / 4;
    if (n_groups > 0) {
        int blocks = (n_groups + BLOCK_THREADS - 1) / BLOCK_THREADS;
        emit_kernel<<<blocks, BLOCK_THREADS>>>(obs, out, n_groups, n_spots);
    }

    int tail_start = n_groups * 4;
    int tail = n_spots_i - tail_start;
    if (tail > 0) {
        emit_tail_kernel<<<(tail + 255) / 256, 256>>>(obs, out, tail_start,
                                                      n_spots_i, n_spots);
    }
}